// round 4
// baseline (speedup 1.0000x reference)
#include <cuda_runtime.h>
#include <cuda_bf16.h>

#define NNODE 21
#define HIDD 128
#define TSTEPS 500
#define NEDGE 210

typedef unsigned long long u64;

// ---------------- packed f32x2 helpers ----------------
__device__ __forceinline__ u64 pk2(float lo, float hi) {
    u64 r; asm("mov.b64 %0,{%1,%2};" : "=l"(r) : "f"(lo), "f"(hi)); return r;
}
__device__ __forceinline__ u64 bc2(float v) {
    u64 r; asm("mov.b64 %0,{%1,%1};" : "=l"(r) : "f"(v)); return r;
}
__device__ __forceinline__ u64 fma2(u64 a, u64 b, u64 c) {
    u64 d; asm("fma.rn.f32x2 %0,%1,%2,%3;" : "=l"(d) : "l"(a), "l"(b), "l"(c)); return d;
}
__device__ __forceinline__ void up2(u64 v, float& lo, float& hi) {
    asm("mov.b64 {%0,%1},%2;" : "=f"(lo), "=f"(hi) : "l"(v));
}

__device__ __forceinline__ float sigm(float v) {
    return __fdividef(1.0f, 1.0f + __expf(-v));
}
__device__ __forceinline__ float tanh_(float v) {
    // tanh(x) = 1 - 2/(e^{2x}+1); saturates correctly for |x| large
    return 1.0f - __fdividef(2.0f, __expf(2.0f * v) + 1.0f);
}

// ---------------- device-global precomputed state ----------------
__device__ float g_A[NNODE * NNODE];        // normalized adjacency (dst-major)
__device__ float g_fold1[6 * HIDD];         // vz, vr, vh, cz, cr, ch (layer 1 folds)
__device__ float g_c2[3 * HIDD];            // layer-2 folded biases (z, r, h)
__device__ float g_W2L[3 * HIDD * HIDD];    // W{z,r,h}_2 @ l{z,r,h}w_2[:128]

// ---------------- setup kernels (deterministic, no atomics) ----------------
__global__ void setup_graph(const int* __restrict__ ei, const float* __restrict__ ew) {
    __shared__ float dinv[NNODE];
    int tid = threadIdx.x;
    if (tid < NNODE) {
        float d = 1.0f;  // self loop weight 1
        for (int e = 0; e < NEDGE; e++)
            if (ei[NEDGE + e] == tid) d += ew[e];
        dinv[tid] = (d > 0.f) ? (1.0f / sqrtf(d)) : 0.0f;
    }
    __syncthreads();
    if (tid < NNODE * NNODE) {
        int i = tid / NNODE;   // dst
        int j = tid % NNODE;   // src
        float a = (i == j) ? dinv[i] * dinv[i] : 0.0f;
        for (int e = 0; e < NEDGE; e++)
            if (ei[e] == j && ei[NEDGE + e] == i)
                a += dinv[j] * ew[e] * dinv[i];
        g_A[tid] = a;
    }
}

__global__ void setup_fold1(const float* Wz, const float* bz, const float* lzw, const float* lzb,
                            const float* Wr, const float* br, const float* lrw, const float* lrb,
                            const float* Wh, const float* bh, const float* lhw, const float* lhb) {
    int f = threadIdx.x;  // 0..127
    const float* Ws[3] = {Wz, Wr, Wh};
    const float* bs[3] = {bz, br, bh};
    const float* ls[3] = {lzw, lrw, lhw};
    const float* lb[3] = {lzb, lrb, lhb};
    for (int g = 0; g < 3; g++) {
        float v = 0.f, c = 0.f;
        for (int q = 0; q < HIDD; q++) {
            float l = ls[g][q * HIDD + f];
            v += Ws[g][q] * l;
            c += bs[g][q] * l;
        }
        g_fold1[g * HIDD + f] = v;
        g_fold1[(3 + g) * HIDD + f] = c + lb[g][f];
    }
}

__global__ void setup_fold2(const float* Wz2, const float* lzw2,
                            const float* Wr2, const float* lrw2,
                            const float* Wh2, const float* lhw2) {
    __shared__ float wrow[HIDD];
    int g = blockIdx.x >> 7;
    int k = blockIdx.x & 127;
    const float* W = (g == 0) ? Wz2 : ((g == 1) ? Wr2 : Wh2);
    const float* L = (g == 0) ? lzw2 : ((g == 1) ? lrw2 : lhw2);
    int f = threadIdx.x;
    wrow[f] = W[k * HIDD + f];
    __syncthreads();
    float a = 0.f;
    for (int q = 0; q < HIDD; q++) a += wrow[q] * L[q * HIDD + f];
    g_W2L[g * HIDD * HIDD + k * HIDD + f] = a;
}

__global__ void setup_c2(const float* bz, const float* lzw, const float* lzb,
                         const float* br, const float* lrw, const float* lrb,
                         const float* bh, const float* lhw, const float* lhb) {
    int f = threadIdx.x;
    const float* bs[3] = {bz, br, bh};
    const float* ls[3] = {lzw, lrw, lhw};
    const float* lb[3] = {lzb, lrb, lhb};
    for (int g = 0; g < 3; g++) {
        float c = 0.f;
        for (int q = 0; q < HIDD; q++) c += bs[g][q] * ls[g][q * HIDD + f];
        g_c2[g * HIDD + f] = c + lb[g][f];
    }
}

// ---------------- matmul micro-kernels (3 rows x 4 cols per thread, f32x2) ----------------
// S rows are read as one 16B LDS broadcast per row per 4 k (dedups to 1 wavefront),
// instead of 4 scalar broadcasts, to cut L1tex wavefront pressure.
struct DA { u64 a0[3], a1[3], b0[3], b1[3]; };
struct SA { u64 a0[3], a1[3]; };

__device__ __forceinline__ void mmd(const float* __restrict__ S,
                                    const float* __restrict__ Ua,
                                    const float* __restrict__ Ub,
                                    int i0, int fg, DA& A) {
    const ulonglong2* Ua2 = reinterpret_cast<const ulonglong2*>(Ua);
    const ulonglong2* Ub2 = reinterpret_cast<const ulonglong2*>(Ub);
#pragma unroll 2
    for (int k4 = 0; k4 < HIDD / 4; k4++) {
        float4 sq[3];
#pragma unroll
        for (int r = 0; r < 3; r++)
            sq[r] = *reinterpret_cast<const float4*>(&S[(i0 + r) * HIDD + k4 * 4]);
        float sa[3][4];
#pragma unroll
        for (int r = 0; r < 3; r++) {
            sa[r][0] = sq[r].x; sa[r][1] = sq[r].y; sa[r][2] = sq[r].z; sa[r][3] = sq[r].w;
        }
#pragma unroll
        for (int kk = 0; kk < 4; kk++) {
            int k = k4 * 4 + kk;
            ulonglong2 ua = Ua2[k * 32 + fg];
            ulonglong2 ub = Ub2[k * 32 + fg];
#pragma unroll
            for (int r = 0; r < 3; r++) {
                u64 s = bc2(sa[r][kk]);
                A.a0[r] = fma2(s, ua.x, A.a0[r]); A.a1[r] = fma2(s, ua.y, A.a1[r]);
                A.b0[r] = fma2(s, ub.x, A.b0[r]); A.b1[r] = fma2(s, ub.y, A.b1[r]);
            }
        }
    }
}

__device__ __forceinline__ void mms(const float* __restrict__ S,
                                    const float* __restrict__ U,
                                    int i0, int fg, SA& A) {
    const ulonglong2* U2 = reinterpret_cast<const ulonglong2*>(U);
#pragma unroll 2
    for (int k4 = 0; k4 < HIDD / 4; k4++) {
        float4 sq[3];
#pragma unroll
        for (int r = 0; r < 3; r++)
            sq[r] = *reinterpret_cast<const float4*>(&S[(i0 + r) * HIDD + k4 * 4]);
        float sa[3][4];
#pragma unroll
        for (int r = 0; r < 3; r++) {
            sa[r][0] = sq[r].x; sa[r][1] = sq[r].y; sa[r][2] = sq[r].z; sa[r][3] = sq[r].w;
        }
#pragma unroll
        for (int kk = 0; kk < 4; kk++) {
            int k = k4 * 4 + kk;
            ulonglong2 u = U2[k * 32 + fg];
#pragma unroll
            for (int r = 0; r < 3; r++) {
                u64 s = bc2(sa[r][kk]);
                A.a0[r] = fma2(s, u.x, A.a0[r]); A.a1[r] = fma2(s, u.y, A.a1[r]);
            }
        }
    }
}

__device__ __forceinline__ void amixd(const float* sA, const float* Ma, const float* Mb,
                                      int i0, int fg, DA& A) {
    const ulonglong2* Ma2 = reinterpret_cast<const ulonglong2*>(Ma);
    const ulonglong2* Mb2 = reinterpret_cast<const ulonglong2*>(Mb);
#pragma unroll
    for (int j = 0; j < NNODE; j++) {
        ulonglong2 ma = Ma2[j * 32 + fg];
        ulonglong2 mb = Mb2[j * 32 + fg];
#pragma unroll
        for (int r = 0; r < 3; r++) {
            u64 a = bc2(sA[(i0 + r) * NNODE + j]);
            A.a0[r] = fma2(a, ma.x, A.a0[r]); A.a1[r] = fma2(a, ma.y, A.a1[r]);
            A.b0[r] = fma2(a, mb.x, A.b0[r]); A.b1[r] = fma2(a, mb.y, A.b1[r]);
        }
    }
}

__device__ __forceinline__ void amixs(const float* sA, const float* Ma,
                                      int i0, int fg, SA& A) {
    const ulonglong2* Ma2 = reinterpret_cast<const ulonglong2*>(Ma);
#pragma unroll
    for (int j = 0; j < NNODE; j++) {
        ulonglong2 ma = Ma2[j * 32 + fg];
#pragma unroll
        for (int r = 0; r < 3; r++) {
            u64 a = bc2(sA[(i0 + r) * NNODE + j]);
            A.a0[r] = fma2(a, ma.x, A.a0[r]); A.a1[r] = fma2(a, ma.y, A.a1[r]);
        }
    }
}

// ---------------- main persistent kernel: one CTA per batch element ----------------
#define SMEM_FLOATS (6 * NNODE * HIDD + 448 + 32 + 9 * HIDD)

__global__ void __launch_bounds__(224, 1) tgcn_main(
    const float* __restrict__ x,
    const float* __restrict__ Uz1, const float* __restrict__ Ur1, const float* __restrict__ Uh1,
    const float* __restrict__ Uz2, const float* __restrict__ Ur2, const float* __restrict__ Uh2,
    const float* __restrict__ clsw, const float* __restrict__ clsb,
    float* __restrict__ out) {
    extern __shared__ float sm[];
    float* sH1 = sm;
    float* sH2 = sH1 + NNODE * HIDD;
    float* sZ  = sH2 + NNODE * HIDD;
    float* sHR = sZ  + NNODE * HIDD;
    float* sMa = sHR + NNODE * HIDD;
    float* sMb = sMa + NNODE * HIDD;
    float* sA  = sMb + NNODE * HIDD;   // 448 (441 used)
    float* sy  = sA + 448;             // 32 (21 used)
    float* sv  = sy + 32;              // 9 * 128
    float* svz = sv,        *svr = sv + 128,  *svh = sv + 256;
    float* scz = sv + 384,  *scr = sv + 512,  *sch = sv + 640;
    float* sc2z = sv + 768, *sc2r = sv + 896, *sc2h = sv + 1024;

    const int tid = threadIdx.x, b = blockIdx.x;
    const int fg = tid & 31, rg = tid >> 5;
    const int i0 = rg * 3, f0 = fg * 4;

    for (int i = tid; i < NNODE * HIDD; i += 224) { sH1[i] = 0.f; sH2[i] = 0.f; }
    for (int i = tid; i < NNODE * NNODE; i += 224) sA[i] = g_A[i];
    if (tid < HIDD) {
        for (int g = 0; g < 6; g++) sv[g * 128 + tid] = g_fold1[g * 128 + tid];
        for (int g = 0; g < 3; g++) sv[(6 + g) * 128 + tid] = g_c2[g * 128 + tid];
    }
    __syncthreads();

    float accS[12];
#pragma unroll
    for (int q = 0; q < 12; q++) accS[q] = 0.f;

    const float* xb = x + (size_t)b * TSTEPS * NNODE;

    for (int t = 0; t < TSTEPS; t++) {
        // y = A @ x_t  (21x21 matvec)
        if (tid < NNODE) {
            const float* xr = xb + t * NNODE;
            float a = 0.f;
#pragma unroll
            for (int j = 0; j < NNODE; j++) a += sA[tid * NNODE + j] * xr[j];
            sy[tid] = a;
        }
        __syncthreads();

        // ---- L1 pass A: Z1 and R1 (fused dual matmul over H1)
        {
            DA acc{};
            mmd(sH1, Uz1, Ur1, i0, fg, acc);
#pragma unroll
            for (int r = 0; r < 3; r++) {
                int i = i0 + r; float yv = sy[i];
                float v[4], w[4];
                up2(acc.a0[r], v[0], v[1]); up2(acc.a1[r], v[2], v[3]);
                up2(acc.b0[r], w[0], w[1]); up2(acc.b1[r], w[2], w[3]);
#pragma unroll
                for (int c = 0; c < 4; c++) {
                    int f = f0 + c, idx = i * HIDD + f;
                    sZ[idx] = sigm(fmaf(yv, svz[f], scz[f]) + v[c]);
                    float rr = sigm(fmaf(yv, svr[f], scr[f]) + w[c]);
                    sHR[idx] = rr * sH1[idx];
                }
            }
        }
        __syncthreads();

        // ---- L1 pass B: Ht1 + blend into H1
        {
            SA acc{};
            mms(sHR, Uh1, i0, fg, acc);
#pragma unroll
            for (int r = 0; r < 3; r++) {
                int i = i0 + r; float yv = sy[i];
                float v[4]; up2(acc.a0[r], v[0], v[1]); up2(acc.a1[r], v[2], v[3]);
#pragma unroll
                for (int c = 0; c < 4; c++) {
                    int f = f0 + c, idx = i * HIDD + f;
                    float hh = tanh_(fmaf(yv, svh[f], sch[f]) + v[c]);
                    float z = sZ[idx], h = sH1[idx];
                    sH1[idx] = fmaf(z, h - hh, hh);   // z*h + (1-z)*hh
                }
            }
        }
        __syncthreads();

        // ---- L2 pass A: Mz = H1 @ WzL, Mr = H1 @ WrL
        {
            DA acc{};
            mmd(sH1, g_W2L, g_W2L + HIDD * HIDD, i0, fg, acc);
#pragma unroll
            for (int r = 0; r < 3; r++) {
                ulonglong2 ta; ta.x = acc.a0[r]; ta.y = acc.a1[r];
                ulonglong2 tb; tb.x = acc.b0[r]; tb.y = acc.b1[r];
                *reinterpret_cast<ulonglong2*>(sMa + (i0 + r) * HIDD + f0) = ta;
                *reinterpret_cast<ulonglong2*>(sMb + (i0 + r) * HIDD + f0) = tb;
            }
        }
        __syncthreads();

        // ---- L2 pass B: Z2 = sig(c2z + A-mix(Mz) + H2@Uz2), HR2 = sig(...)·H2
        {
            DA acc;
            u64 ca0 = pk2(sc2z[f0], sc2z[f0 + 1]), ca1 = pk2(sc2z[f0 + 2], sc2z[f0 + 3]);
            u64 cb0 = pk2(sc2r[f0], sc2r[f0 + 1]), cb1 = pk2(sc2r[f0 + 2], sc2r[f0 + 3]);
#pragma unroll
            for (int r = 0; r < 3; r++) { acc.a0[r] = ca0; acc.a1[r] = ca1; acc.b0[r] = cb0; acc.b1[r] = cb1; }
            amixd(sA, sMa, sMb, i0, fg, acc);
            mmd(sH2, Uz2, Ur2, i0, fg, acc);
#pragma unroll
            for (int r = 0; r < 3; r++) {
                int i = i0 + r;
                float v[4], w[4];
                up2(acc.a0[r], v[0], v[1]); up2(acc.a1[r], v[2], v[3]);
                up2(acc.b0[r], w[0], w[1]); up2(acc.b1[r], w[2], w[3]);
#pragma unroll
                for (int c = 0; c < 4; c++) {
                    int f = f0 + c, idx = i * HIDD + f;
                    sZ[idx] = sigm(v[c]);
                    sHR[idx] = sigm(w[c]) * sH2[idx];
                }
            }
        }
        __syncthreads();

        // ---- L2 pass C: Mh = H1 @ WhL
        {
            SA acc{};
            mms(sH1, g_W2L + 2 * HIDD * HIDD, i0, fg, acc);
#pragma unroll
            for (int r = 0; r < 3; r++) {
                ulonglong2 ta; ta.x = acc.a0[r]; ta.y = acc.a1[r];
                *reinterpret_cast<ulonglong2*>(sMa + (i0 + r) * HIDD + f0) = ta;
            }
        }
        __syncthreads();

        // ---- L2 pass D: Ht2 + blend into H2 + accumulate output sum
        {
            SA acc;
            u64 c0 = pk2(sc2h[f0], sc2h[f0 + 1]), c1 = pk2(sc2h[f0 + 2], sc2h[f0 + 3]);
#pragma unroll
            for (int r = 0; r < 3; r++) { acc.a0[r] = c0; acc.a1[r] = c1; }
            amixs(sA, sMa, i0, fg, acc);
            mms(sHR, Uh2, i0, fg, acc);
#pragma unroll
            for (int r = 0; r < 3; r++) {
                int i = i0 + r;
                float v[4]; up2(acc.a0[r], v[0], v[1]); up2(acc.a1[r], v[2], v[3]);
#pragma unroll
                for (int c = 0; c < 4; c++) {
                    int f = f0 + c, idx = i * HIDD + f;
                    float hh = tanh_(v[c]);
                    float z = sZ[idx], h = sH2[idx];
                    float hn = fmaf(z, h - hh, hh);
                    sH2[idx] = hn;
                    accS[r * 4 + c] += hn;
                }
            }
        }
        __syncthreads();
    }

    // ---- final reduction: seq_out = sum/(N*T); out[b] = seq_out @ cls_w + cls_b
    {
        float cs0 = accS[0] + accS[4] + accS[8];
        float cs1 = accS[1] + accS[5] + accS[9];
        float cs2 = accS[2] + accS[6] + accS[10];
        float cs3 = accS[3] + accS[7] + accS[11];
        sMa[rg * HIDD + f0 + 0] = cs0;
        sMa[rg * HIDD + f0 + 1] = cs1;
        sMa[rg * HIDD + f0 + 2] = cs2;
        sMa[rg * HIDD + f0 + 3] = cs3;
    }
    __syncthreads();
    if (tid < HIDD) {
        float s = 0.f;
#pragma unroll
        for (int r = 0; r < 7; r++) s += sMa[r * HIDD + tid];
        s *= (1.0f / (float)(NNODE * TSTEPS));
        sMb[tid] = s * clsw[tid];
    }
    __syncthreads();
    if (tid == 0) {
        float s = 0.f;
        for (int f = 0; f < HIDD; f++) s += sMb[f];
        out[b] = s + clsb[0];
    }
}

// ---------------- launch ----------------
extern "C" void kernel_launch(void* const* d_in, const int* in_sizes, int n_in,
                              void* d_out, int out_size) {
    const float* x    = (const float*)d_in[0];
    const int*   ei   = (const int*)d_in[1];
    const float* ew   = (const float*)d_in[2];
    const float* Wz1  = (const float*)d_in[3];
    const float* bz1  = (const float*)d_in[4];
    const float* lzw1 = (const float*)d_in[5];
    const float* lzb1 = (const float*)d_in[6];
    const float* Wr1  = (const float*)d_in[7];
    const float* br1  = (const float*)d_in[8];
    const float* lrw1 = (const float*)d_in[9];
    const float* lrb1 = (const float*)d_in[10];
    const float* Wh1  = (const float*)d_in[11];
    const float* bh1  = (const float*)d_in[12];
    const float* lhw1 = (const float*)d_in[13];
    const float* lhb1 = (const float*)d_in[14];
    const float* Wz2  = (const float*)d_in[15];
    const float* bz2  = (const float*)d_in[16];
    const float* lzw2 = (const float*)d_in[17];
    const float* lzb2 = (const float*)d_in[18];
    const float* Wr2  = (const float*)d_in[19];
    const float* br2  = (const float*)d_in[20];
    const float* lrw2 = (const float*)d_in[21];
    const float* lrb2 = (const float*)d_in[22];
    const float* Wh2  = (const float*)d_in[23];
    const float* bh2  = (const float*)d_in[24];
    const float* lhw2 = (const float*)d_in[25];
    const float* lhb2 = (const float*)d_in[26];
    const float* clsw = (const float*)d_in[27];
    const float* clsb = (const float*)d_in[28];
    float* out = (float*)d_out;

    setup_graph<<<1, 448>>>(ei, ew);
    setup_fold1<<<1, 128>>>(Wz1, bz1, lzw1, lzb1, Wr1, br1, lrw1, lrb1, Wh1, bh1, lhw1, lhb1);
    setup_fold2<<<384, 128>>>(Wz2, lzw2, Wr2, lrw2, Wh2, lhw2);
    setup_c2<<<1, 128>>>(bz2, lzw2, lzb2, br2, lrw2, lrb2, bh2, lhw2, lhb2);

    const int smem_bytes = SMEM_FLOATS * (int)sizeof(float);  // 71040
    cudaFuncSetAttribute(tgcn_main, cudaFuncAttributeMaxDynamicSharedMemorySize, smem_bytes);
    tgcn_main<<<64, 224, smem_bytes>>>(
        x,
        lzw1 + HIDD * HIDD, lrw1 + HIDD * HIDD, lhw1 + HIDD * HIDD,
        lzw2 + HIDD * HIDD, lrw2 + HIDD * HIDD, lhw2 + HIDD * HIDD,
        clsw, clsb, out);
}